// round 13
// baseline (speedup 1.0000x reference)
#include <cuda_runtime.h>
#include <cuda_fp16.h>
#include <cstdint>

// CapsuleLayer: v = routing(reshape(x @ W, [B,16,32]))
//   x: [32768, 512] f32, W: [512, 512] f32, out v: [32768, 32] f32
//
// K1: split_W -> g_Wp (hi/lo fp16 pairs, k-major), 4-wide vectorized
// K2: GEMM u = hh + hl + lh (fp32-accurate FP16 split, m16n8k16),
//     tile 128x64 (2048 CTAs -> 7 waves, ~1% quantization loss vs 13% at 128x128),
//     3-stage cp.async pipeline for B, LDG+pack+STS for A -> g_u
// K3: routing, 2 rows per warp (dual interleaved shuffle chains) -> out

#define K_DIM 512
#define N_DIM 512
#define NUM_CAPS 16
#define OUT_DIM 32
#define MAX_BATCH 32768
#define NKPALL (K_DIM / 2)

#define BM 128
#define BN 64
#define BK 16
#define NKP (BK / 2)            // 8 k-pairs per stage
#define NKT (K_DIM / BK)        // 32 stages
#define NSTG 3                  // smem ring depth
#define XTS 132                 // A tile row stride (uint2 units)
#define WTS 68                  // B tile row stride (uint2 units)

#define XS_BYTES (NSTG * NKP * XTS * 8)     // 25344
#define WS_BYTES (NSTG * NKP * WTS * 8)     // 13056
#define SMEM_POOL (XS_BYTES + WS_BYTES)     // 38400 -> 2 CTAs/SM easily

__device__ float g_u[(size_t)MAX_BATCH * N_DIM];      // 64 MB
__device__ uint2 g_Wp[(size_t)NKPALL * N_DIM];        // 2 MB

__device__ __forceinline__ void split16(float x, __half& h, __half& l) {
    h = __float2half_rn(x);
    l = __float2half_rn(x - __half2float(h));
}
__device__ __forceinline__ uint2 pack_pair(float v0, float v1) {
    __half h0, l0, h1, l1;
    split16(v0, h0, l0);
    split16(v1, h1, l1);
    uint2 r;
    __half2 hh = __halves2half2(h0, h1);
    __half2 ll = __halves2half2(l0, l1);
    r.x = *reinterpret_cast<uint32_t*>(&hh);
    r.y = *reinterpret_cast<uint32_t*>(&ll);
    return r;
}
__device__ __forceinline__ void mma_m16n8k16_f16(float d[4], const uint32_t a[4],
                                                 const uint32_t b[2]) {
    asm volatile(
        "mma.sync.aligned.m16n8k16.row.col.f32.f16.f16.f32 "
        "{%0,%1,%2,%3}, {%4,%5,%6,%7}, {%8,%9}, {%0,%1,%2,%3};\n"
        : "+f"(d[0]), "+f"(d[1]), "+f"(d[2]), "+f"(d[3])
        : "r"(a[0]), "r"(a[1]), "r"(a[2]), "r"(a[3]), "r"(b[0]), "r"(b[1]));
}
__device__ __forceinline__ uint32_t smem_u32(const void* p) {
    return (uint32_t)__cvta_generic_to_shared(p);
}
__device__ __forceinline__ void cp_async16(uint32_t dst, const void* src) {
    asm volatile("cp.async.cg.shared.global [%0], [%1], 16;\n"
                 :: "r"(dst), "l"(src) : "memory");
}

// ---------------------------------------------------------------------------
// K1: W [512 k][512 n] f32 -> g_Wp [256 kp][512 n] uint2, 4 n per thread
// ---------------------------------------------------------------------------
__global__ void split_w_kernel(const float* __restrict__ W) {
    const int idx = blockIdx.x * blockDim.x + threadIdx.x;   // 32768 threads
    const int kp = idx >> 7;
    const int n4 = (idx & 127) << 2;
    float4 r0 = *reinterpret_cast<const float4*>(W + (size_t)(2 * kp) * N_DIM + n4);
    float4 r1 = *reinterpret_cast<const float4*>(W + (size_t)(2 * kp + 1) * N_DIM + n4);
    uint2* dst = &g_Wp[(size_t)kp * N_DIM + n4];
    uint2 p0 = pack_pair(r0.x, r1.x);
    uint2 p1 = pack_pair(r0.y, r1.y);
    uint2 p2 = pack_pair(r0.z, r1.z);
    uint2 p3 = pack_pair(r0.w, r1.w);
    *reinterpret_cast<uint4*>(dst)     = make_uint4(p0.x, p0.y, p1.x, p1.y);
    *reinterpret_cast<uint4*>(dst + 2) = make_uint4(p2.x, p2.y, p3.x, p3.y);
}

// ---------------------------------------------------------------------------
// K2: GEMM C[M,512] = X @ W, 128x64 tile, 256 thr (8 warps, 4m x 2n),
// warp tile 32x32 = 2 x 4 m16n8k16 frags, 3-stage cp.async pipeline.
// ---------------------------------------------------------------------------
__global__ void __launch_bounds__(256, 2)
capsule_gemm_kernel(const float* __restrict__ X) {
    extern __shared__ __align__(16) char smem[];
    typedef uint2 XTile[NKP][XTS];
    typedef uint2 WTile[NKP][WTS];
    XTile* Xs = reinterpret_cast<XTile*>(smem);                 // [NSTG]
    WTile* Ws = reinterpret_cast<WTile*>(smem + XS_BYTES);      // [NSTG]

    const int tid = threadIdx.x;
    const int n0 = blockIdx.x * BN;   // n fast-varying -> X tile L2 reuse
    const int m0 = blockIdx.y * BM;

    const int warp = tid >> 5;
    const int lane = tid & 31;
    const int wm = warp >> 1;         // 0..3 -> 32 rows
    const int wn = warp & 1;          // 0..1 -> 32 cols
    const int g = lane >> 2;          // 0..7
    const int t = lane & 3;           // 0..3

    // A staging: row xr (0..127), 8 k at xk8 (0 or 8) -> 4 kp
    const int xr  = tid >> 1;
    const int xk8 = (tid & 1) << 3;
    const int p0  = (tid & 1) << 2;
    // B staging (cp.async): kp row wkp (0..7), 2 uint2 at wn2 -> one 16B copy
    const int wkp = tid >> 5;
    const int wn2 = (tid & 31) << 1;  // 0..62

    float acc[2][4][4];
#pragma unroll
    for (int i = 0; i < 2; i++)
#pragma unroll
        for (int j = 0; j < 4; j++)
#pragma unroll
            for (int q = 0; q < 4; q++) acc[i][j][q] = 0.f;

    const float* Asrc = X + (size_t)(m0 + xr) * K_DIM + xk8;
    const uint2* Bsrc = g_Wp + (size_t)wkp * N_DIM + n0 + wn2;

    float4 xa0, xa1;

    auto ldgA = [&](int kt) {
        xa0 = *reinterpret_cast<const float4*>(Asrc + kt * BK);
        xa1 = *reinterpret_cast<const float4*>(Asrc + kt * BK + 4);
    };
    auto stsA = [&](int s) {
        Xs[s][p0 + 0][xr] = pack_pair(xa0.x, xa0.y);
        Xs[s][p0 + 1][xr] = pack_pair(xa0.z, xa0.w);
        Xs[s][p0 + 2][xr] = pack_pair(xa1.x, xa1.y);
        Xs[s][p0 + 3][xr] = pack_pair(xa1.z, xa1.w);
    };
    auto asyncB = [&](int kt, int s) {
        const uint2* src = Bsrc + (size_t)kt * NKP * N_DIM;
        cp_async16(smem_u32(&Ws[s][wkp][wn2]), src);
        asm volatile("cp.async.commit_group;\n" ::: "memory");
    };

    // term-inner compute (proven order, bit-identical accumulation)
    auto compute = [&](int s) {
        uint32_t aH[2][4], aL[2][4];
#pragma unroll
        for (int i = 0; i < 2; i++) {
            const int mr = wm * 32 + i * 16 + g;
            uint2 A0 = Xs[s][t][mr];
            uint2 A1 = Xs[s][t][mr + 8];
            uint2 A2 = Xs[s][t + 4][mr];
            uint2 A3 = Xs[s][t + 4][mr + 8];
            aH[i][0] = A0.x; aL[i][0] = A0.y;
            aH[i][1] = A1.x; aL[i][1] = A1.y;
            aH[i][2] = A2.x; aL[i][2] = A2.y;
            aH[i][3] = A3.x; aL[i][3] = A3.y;
        }
#pragma unroll
        for (int j = 0; j < 4; j++) {
            const int nc = wn * 32 + j * 8 + g;
            uint2 B0 = Ws[s][t][nc];
            uint2 B1 = Ws[s][t + 4][nc];
            uint32_t bH[2] = {B0.x, B1.x};
            uint32_t bL[2] = {B0.y, B1.y};
#pragma unroll
            for (int i = 0; i < 2; i++) {
                mma_m16n8k16_f16(acc[i][j], aH[i], bH);
                mma_m16n8k16_f16(acc[i][j], aH[i], bL);
                mma_m16n8k16_f16(acc[i][j], aL[i], bH);
            }
        }
    };

    // prologue: fill stages 0, 1 (R8 schedule)
    ldgA(0); asyncB(0, 0); stsA(0);
    ldgA(1); asyncB(1, 1); stsA(1);
    asm volatile("cp.async.wait_group 1;\n" ::: "memory");   // B0 done
    __syncthreads();

    int s = 0;
    for (int kt = 0; kt < NKT; kt++) {
        if (kt + 2 < NKT) {
            ldgA(kt + 2);
            asyncB(kt + 2, (s + 2 >= NSTG) ? s + 2 - NSTG : s + 2);
        }
        compute(s);
        if (kt + 2 < NKT) stsA((s + 2 >= NSTG) ? s + 2 - NSTG : s + 2);
        if (kt + 1 < NKT) {
            if (kt + 2 < NKT)
                asm volatile("cp.async.wait_group 1;\n" ::: "memory");
            else
                asm volatile("cp.async.wait_group 0;\n" ::: "memory");
            __syncthreads();
        }
        s = (s + 1 >= NSTG) ? 0 : s + 1;
    }

    // epilogue -> g_u
#pragma unroll
    for (int i = 0; i < 2; i++) {
#pragma unroll
        for (int j = 0; j < 4; j++) {
            const int row = m0 + wm * 32 + i * 16 + g;
            const int col = n0 + wn * 32 + j * 8 + t * 2;
            *reinterpret_cast<float2*>(&g_u[(size_t)row * N_DIM + col]) =
                make_float2(acc[i][j][0], acc[i][j][1]);
            *reinterpret_cast<float2*>(&g_u[(size_t)(row + 8) * N_DIM + col]) =
                make_float2(acc[i][j][2], acc[i][j][3]);
        }
    }
}

// ---------------------------------------------------------------------------
// K3: routing, one warp per TWO rows (dual interleaved chains), lane = dim.
// ---------------------------------------------------------------------------
__device__ __forceinline__ void rs16_dual(float p[NUM_CAPS], float q[NUM_CAPS],
                                          int lane, float& r0, float& r1) {
    {
        const bool low = (lane & 16) == 0;
#pragma unroll
        for (int i = 0; i < 8; i++) {
            float s0 = low ? p[i + 8] : p[i];
            float s1 = low ? q[i + 8] : q[i];
            float v0 = __shfl_xor_sync(0xffffffffu, s0, 16);
            float v1 = __shfl_xor_sync(0xffffffffu, s1, 16);
            p[i] = (low ? p[i] : p[i + 8]) + v0;
            q[i] = (low ? q[i] : q[i + 8]) + v1;
        }
    }
    {
        const bool low = (lane & 8) == 0;
#pragma unroll
        for (int i = 0; i < 4; i++) {
            float s0 = low ? p[i + 4] : p[i];
            float s1 = low ? q[i + 4] : q[i];
            float v0 = __shfl_xor_sync(0xffffffffu, s0, 8);
            float v1 = __shfl_xor_sync(0xffffffffu, s1, 8);
            p[i] = (low ? p[i] : p[i + 4]) + v0;
            q[i] = (low ? q[i] : q[i + 4]) + v1;
        }
    }
    {
        const bool low = (lane & 4) == 0;
#pragma unroll
        for (int i = 0; i < 2; i++) {
            float s0 = low ? p[i + 2] : p[i];
            float s1 = low ? q[i + 2] : q[i];
            float v0 = __shfl_xor_sync(0xffffffffu, s0, 4);
            float v1 = __shfl_xor_sync(0xffffffffu, s1, 4);
            p[i] = (low ? p[i] : p[i + 2]) + v0;
            q[i] = (low ? q[i] : q[i + 2]) + v1;
        }
    }
    {
        const bool low = (lane & 2) == 0;
        float s0 = low ? p[1] : p[0];
        float s1 = low ? q[1] : q[0];
        float v0 = __shfl_xor_sync(0xffffffffu, s0, 2);
        float v1 = __shfl_xor_sync(0xffffffffu, s1, 2);
        p[0] = (low ? p[0] : p[1]) + v0;
        q[0] = (low ? q[0] : q[1]) + v1;
    }
    r0 = p[0] + __shfl_xor_sync(0xffffffffu, p[0], 1);
    r1 = q[0] + __shfl_xor_sync(0xffffffffu, q[0], 1);
}

__device__ __forceinline__ void squash2(float s0, float s1, float& v0, float& v1) {
    float n0 = s0 * s0, n1 = s1 * s1;
#pragma unroll
    for (int o = 16; o; o >>= 1) {
        n0 += __shfl_xor_sync(0xffffffffu, n0, o);
        n1 += __shfl_xor_sync(0xffffffffu, n1, o);
    }
    v0 = (n0 / (1.f + n0)) / (sqrtf(n0) + 1e-8f) * s0;
    v1 = (n1 / (1.f + n1)) / (sqrtf(n1) + 1e-8f) * s1;
}

__global__ void __launch_bounds__(256)
capsule_routing_kernel(float* __restrict__ out, int batch) {
    const int gw = (int)((blockIdx.x * blockDim.x + threadIdx.x) >> 5);
    const int lane = threadIdx.x & 31;
    const int row0 = gw * 2;
    if (row0 >= batch) return;

    const float* ur0 = g_u + (size_t)row0 * N_DIM;
    const float* ur1 = ur0 + N_DIM;
    float u0[NUM_CAPS], u1[NUM_CAPS];
#pragma unroll
    for (int c = 0; c < NUM_CAPS; c++) {
        u0[c] = ur0[c * OUT_DIM + lane];
        u1[c] = ur1[c * OUT_DIM + lane];
    }

    float b0 = 0.f, b1 = 0.f;
    float v0, v1;

    {
        float s0 = u0[0], s1 = u1[0];
#pragma unroll
        for (int c = 1; c < NUM_CAPS; c++) { s0 += u0[c]; s1 += u1[c]; }
        s0 *= (1.f / 16.f); s1 *= (1.f / 16.f);
        squash2(s0, s1, v0, v1);
        float p[NUM_CAPS], q[NUM_CAPS];
#pragma unroll
        for (int c = 0; c < NUM_CAPS; c++) { p[c] = u0[c] * v0; q[c] = u1[c] * v1; }
        float d0, d1;
        rs16_dual(p, q, lane, d0, d1);
        b0 += d0; b1 += d1;
    }

#pragma unroll
    for (int it = 1; it < 3; it++) {
        float m0 = b0, m1 = b1;
#pragma unroll
        for (int o = 2; o <= 16; o <<= 1) {
            m0 = fmaxf(m0, __shfl_xor_sync(0xffffffffu, m0, o));
            m1 = fmaxf(m1, __shfl_xor_sync(0xffffffffu, m1, o));
        }
        float e0 = __expf(b0 - m0), e1 = __expf(b1 - m1);
        float t0 = e0, t1 = e1;
#pragma unroll
        for (int o = 2; o <= 16; o <<= 1) {
            t0 += __shfl_xor_sync(0xffffffffu, t0, o);
            t1 += __shfl_xor_sync(0xffffffffu, t1, o);
        }
        const float cw0 = e0 / t0, cw1 = e1 / t1;

        float s0 = 0.f, s1 = 0.f;
#pragma unroll
        for (int c = 0; c < NUM_CAPS; c++) {
            s0 = fmaf(__shfl_sync(0xffffffffu, cw0, 2 * c), u0[c], s0);
            s1 = fmaf(__shfl_sync(0xffffffffu, cw1, 2 * c), u1[c], s1);
        }
        squash2(s0, s1, v0, v1);

        if (it < 2) {
            float p[NUM_CAPS], q[NUM_CAPS];
#pragma unroll
            for (int c = 0; c < NUM_CAPS; c++) { p[c] = u0[c] * v0; q[c] = u1[c] * v1; }
            float d0, d1;
            rs16_dual(p, q, lane, d0, d1);
            b0 += d0; b1 += d1;
        }
    }

    out[(size_t)row0 * OUT_DIM + lane] = v0;
    out[(size_t)(row0 + 1) * OUT_DIM + lane] = v1;
}

// ---------------------------------------------------------------------------
extern "C" void kernel_launch(void* const* d_in, const int* in_sizes, int n_in,
                              void* d_out, int out_size) {
    const float* X = (const float*)d_in[0];   // [batch, 512]
    const float* W = (const float*)d_in[1];   // [512, 512]
    float* out = (float*)d_out;               // [batch, 32]

    const int batch = in_sizes[0] / K_DIM;    // 32768

    split_w_kernel<<<128, 256>>>(W);

    cudaFuncSetAttribute(capsule_gemm_kernel,
                         cudaFuncAttributeMaxDynamicSharedMemorySize, SMEM_POOL);
    dim3 ggrid(N_DIM / BN, batch / BM);       // (8, 256) = 2048 CTAs
    capsule_gemm_kernel<<<ggrid, 256, SMEM_POOL>>>(X);

    const int rwarps = batch / 2;             // 2 rows per warp
    capsule_routing_kernel<<<(rwarps * 32) / 256, 256>>>(out, batch);
}

// round 14
// speedup vs baseline: 1.1327x; 1.1327x over previous
#include <cuda_runtime.h>
#include <cuda_fp16.h>
#include <cstdint>

// CapsuleLayer: v = routing(reshape(x @ W, [B,16,32]))
//   x: [32768, 512] f32, W: [512, 512] f32, out v: [32768, 32] f32
//
// CONVERGED CONFIG (R8 champion):
// K1: split_W -> g_Wp (hi/lo fp16 pairs, k-major), 4-wide vectorized
// K2: GEMM u = hh + hl + lh (fp32-accurate FP16 split, m16n8k16),
//     128x128 tile, 3-stage cp.async pipeline for B, LDG+pack+STS for A -> g_u
//     (93% of measured mma.sync HMMA ceiling; tcgen05 blocked by compute_103 PTX)
// K3: routing, 2 rows per warp (dual interleaved shuffle chains) -> out

#define K_DIM 512
#define N_DIM 512
#define NUM_CAPS 16
#define OUT_DIM 32
#define MAX_BATCH 32768
#define NKPALL (K_DIM / 2)

#define BM 128
#define BN 128
#define BK 16
#define NKP (BK / 2)            // 8 k-pairs per stage
#define NKT (K_DIM / BK)        // 32 stages
#define NSTG 3                  // smem ring depth
#define TS 132                  // tile row stride (uint2 units)

#define TILE_BYTES (NSTG * NKP * TS * 8)
#define SMEM_POOL (2 * TILE_BYTES)    // 50688 -> 2 CTAs/SM

__device__ float g_u[(size_t)MAX_BATCH * N_DIM];      // 64 MB
__device__ uint2 g_Wp[(size_t)NKPALL * N_DIM];        // 2 MB

__device__ __forceinline__ void split16(float x, __half& h, __half& l) {
    h = __float2half_rn(x);
    l = __float2half_rn(x - __half2float(h));
}
__device__ __forceinline__ uint2 pack_pair(float v0, float v1) {
    __half h0, l0, h1, l1;
    split16(v0, h0, l0);
    split16(v1, h1, l1);
    uint2 r;
    __half2 hh = __halves2half2(h0, h1);
    __half2 ll = __halves2half2(l0, l1);
    r.x = *reinterpret_cast<uint32_t*>(&hh);
    r.y = *reinterpret_cast<uint32_t*>(&ll);
    return r;
}
__device__ __forceinline__ void mma_m16n8k16_f16(float d[4], const uint32_t a[4],
                                                 const uint32_t b[2]) {
    asm volatile(
        "mma.sync.aligned.m16n8k16.row.col.f32.f16.f16.f32 "
        "{%0,%1,%2,%3}, {%4,%5,%6,%7}, {%8,%9}, {%0,%1,%2,%3};\n"
        : "+f"(d[0]), "+f"(d[1]), "+f"(d[2]), "+f"(d[3])
        : "r"(a[0]), "r"(a[1]), "r"(a[2]), "r"(a[3]), "r"(b[0]), "r"(b[1]));
}
__device__ __forceinline__ uint32_t smem_u32(const void* p) {
    return (uint32_t)__cvta_generic_to_shared(p);
}
__device__ __forceinline__ void cp_async16(uint32_t dst, const void* src) {
    asm volatile("cp.async.cg.shared.global [%0], [%1], 16;\n"
                 :: "r"(dst), "l"(src) : "memory");
}

// ---------------------------------------------------------------------------
// K1: W [512 k][512 n] f32 -> g_Wp [256 kp][512 n] uint2, 4 n per thread
// ---------------------------------------------------------------------------
__global__ void split_w_kernel(const float* __restrict__ W) {
    const int idx = blockIdx.x * blockDim.x + threadIdx.x;   // 32768 threads
    const int kp = idx >> 7;
    const int n4 = (idx & 127) << 2;
    float4 r0 = *reinterpret_cast<const float4*>(W + (size_t)(2 * kp) * N_DIM + n4);
    float4 r1 = *reinterpret_cast<const float4*>(W + (size_t)(2 * kp + 1) * N_DIM + n4);
    uint2* dst = &g_Wp[(size_t)kp * N_DIM + n4];
    uint2 p0 = pack_pair(r0.x, r1.x);
    uint2 p1 = pack_pair(r0.y, r1.y);
    uint2 p2 = pack_pair(r0.z, r1.z);
    uint2 p3 = pack_pair(r0.w, r1.w);
    *reinterpret_cast<uint4*>(dst)     = make_uint4(p0.x, p0.y, p1.x, p1.y);
    *reinterpret_cast<uint4*>(dst + 2) = make_uint4(p2.x, p2.y, p3.x, p3.y);
}

// ---------------------------------------------------------------------------
// K2: GEMM C[M,512] = X @ W, 128x128 tile, 256 thr (8 warps, 4m x 2n),
// warp tile 32x64 = 2 x 8 m16n8k16 frags, 3-stage cp.async pipeline.
// ---------------------------------------------------------------------------
__global__ void __launch_bounds__(256, 2)
capsule_gemm_kernel(const float* __restrict__ X) {
    extern __shared__ __align__(16) char smem[];
    typedef uint2 Tile[NKP][TS];
    Tile* Xs = reinterpret_cast<Tile*>(smem);                 // [NSTG]
    Tile* Ws = reinterpret_cast<Tile*>(smem + TILE_BYTES);    // [NSTG]

    const int tid = threadIdx.x;
    const int n0 = blockIdx.x * BN;
    const int m0 = blockIdx.y * BM;

    const int warp = tid >> 5;
    const int lane = tid & 31;
    const int wm = warp >> 1;
    const int wn = warp & 1;
    const int g = lane >> 2;
    const int t = lane & 3;

    // A staging: row xr, 8 k at xk8 -> 4 kp
    const int xr  = tid >> 1;
    const int xk8 = (tid & 1) << 3;
    const int p0  = (tid & 1) << 2;
    // B staging (cp.async): kp row wkp, 4 uint2 at wn4 (2 x 16B)
    const int wkp = tid >> 5;
    const int wn4 = (tid & 31) << 2;

    float acc[2][8][4];
#pragma unroll
    for (int i = 0; i < 2; i++)
#pragma unroll
        for (int j = 0; j < 8; j++)
#pragma unroll
            for (int q = 0; q < 4; q++) acc[i][j][q] = 0.f;

    const float* Asrc = X + (size_t)(m0 + xr) * K_DIM + xk8;
    const uint2* Bsrc = g_Wp + (size_t)wkp * N_DIM + n0 + wn4;

    float4 xa0, xa1;

    auto ldgA = [&](int kt) {
        xa0 = *reinterpret_cast<const float4*>(Asrc + kt * BK);
        xa1 = *reinterpret_cast<const float4*>(Asrc + kt * BK + 4);
    };
    auto stsA = [&](int s) {
        Xs[s][p0 + 0][xr] = pack_pair(xa0.x, xa0.y);
        Xs[s][p0 + 1][xr] = pack_pair(xa0.z, xa0.w);
        Xs[s][p0 + 2][xr] = pack_pair(xa1.x, xa1.y);
        Xs[s][p0 + 3][xr] = pack_pair(xa1.z, xa1.w);
    };
    auto asyncB = [&](int kt, int s) {
        const uint2* src = Bsrc + (size_t)kt * NKP * N_DIM;
        const uint32_t dst = smem_u32(&Ws[s][wkp][wn4]);
        cp_async16(dst, src);
        cp_async16(dst + 16, src + 2);
        asm volatile("cp.async.commit_group;\n" ::: "memory");
    };

    // term-inner compute (champion order, bit-identical accumulation)
    auto compute = [&](int s) {
        uint32_t aH[2][4], aL[2][4];
#pragma unroll
        for (int i = 0; i < 2; i++) {
            const int mr = wm * 32 + i * 16 + g;
            uint2 A0 = Xs[s][t][mr];
            uint2 A1 = Xs[s][t][mr + 8];
            uint2 A2 = Xs[s][t + 4][mr];
            uint2 A3 = Xs[s][t + 4][mr + 8];
            aH[i][0] = A0.x; aL[i][0] = A0.y;
            aH[i][1] = A1.x; aL[i][1] = A1.y;
            aH[i][2] = A2.x; aL[i][2] = A2.y;
            aH[i][3] = A3.x; aL[i][3] = A3.y;
        }
#pragma unroll
        for (int j = 0; j < 8; j++) {
            const int nc = wn * 64 + j * 8 + g;
            uint2 B0 = Ws[s][t][nc];
            uint2 B1 = Ws[s][t + 4][nc];
            uint32_t bH[2] = {B0.x, B1.x};
            uint32_t bL[2] = {B0.y, B1.y};
#pragma unroll
            for (int i = 0; i < 2; i++) {
                mma_m16n8k16_f16(acc[i][j], aH[i], bH);
                mma_m16n8k16_f16(acc[i][j], aH[i], bL);
                mma_m16n8k16_f16(acc[i][j], aL[i], bH);
            }
        }
    };

    // prologue: fill stages 0, 1
    ldgA(0); asyncB(0, 0); stsA(0);
    ldgA(1); asyncB(1, 1); stsA(1);
    asm volatile("cp.async.wait_group 1;\n" ::: "memory");   // B0 done
    __syncthreads();

    int s = 0;
    for (int kt = 0; kt < NKT; kt++) {
        if (kt + 2 < NKT) {
            ldgA(kt + 2);
            asyncB(kt + 2, (s + 2 >= NSTG) ? s + 2 - NSTG : s + 2);
        }
        compute(s);
        if (kt + 2 < NKT) stsA((s + 2 >= NSTG) ? s + 2 - NSTG : s + 2);
        if (kt + 1 < NKT) {
            if (kt + 2 < NKT)
                asm volatile("cp.async.wait_group 1;\n" ::: "memory");
            else
                asm volatile("cp.async.wait_group 0;\n" ::: "memory");
            __syncthreads();
        }
        s = (s + 1 >= NSTG) ? 0 : s + 1;
    }

    // epilogue -> g_u
#pragma unroll
    for (int i = 0; i < 2; i++) {
#pragma unroll
        for (int j = 0; j < 8; j++) {
            const int row = m0 + wm * 32 + i * 16 + g;
            const int col = n0 + wn * 64 + j * 8 + t * 2;
            *reinterpret_cast<float2*>(&g_u[(size_t)row * N_DIM + col]) =
                make_float2(acc[i][j][0], acc[i][j][1]);
            *reinterpret_cast<float2*>(&g_u[(size_t)(row + 8) * N_DIM + col]) =
                make_float2(acc[i][j][2], acc[i][j][3]);
        }
    }
}

// ---------------------------------------------------------------------------
// K3: routing, one warp per TWO rows (dual interleaved chains), lane = dim.
// ---------------------------------------------------------------------------
__device__ __forceinline__ void rs16_dual(float p[NUM_CAPS], float q[NUM_CAPS],
                                          int lane, float& r0, float& r1) {
    {
        const bool low = (lane & 16) == 0;
#pragma unroll
        for (int i = 0; i < 8; i++) {
            float s0 = low ? p[i + 8] : p[i];
            float s1 = low ? q[i + 8] : q[i];
            float v0 = __shfl_xor_sync(0xffffffffu, s0, 16);
            float v1 = __shfl_xor_sync(0xffffffffu, s1, 16);
            p[i] = (low ? p[i] : p[i + 8]) + v0;
            q[i] = (low ? q[i] : q[i + 8]) + v1;
        }
    }
    {
        const bool low = (lane & 8) == 0;
#pragma unroll
        for (int i = 0; i < 4; i++) {
            float s0 = low ? p[i + 4] : p[i];
            float s1 = low ? q[i + 4] : q[i];
            float v0 = __shfl_xor_sync(0xffffffffu, s0, 8);
            float v1 = __shfl_xor_sync(0xffffffffu, s1, 8);
            p[i] = (low ? p[i] : p[i + 4]) + v0;
            q[i] = (low ? q[i] : q[i + 4]) + v1;
        }
    }
    {
        const bool low = (lane & 4) == 0;
#pragma unroll
        for (int i = 0; i < 2; i++) {
            float s0 = low ? p[i + 2] : p[i];
            float s1 = low ? q[i + 2] : q[i];
            float v0 = __shfl_xor_sync(0xffffffffu, s0, 4);
            float v1 = __shfl_xor_sync(0xffffffffu, s1, 4);
            p[i] = (low ? p[i] : p[i + 2]) + v0;
            q[i] = (low ? q[i] : q[i + 2]) + v1;
        }
    }
    {
        const bool low = (lane & 2) == 0;
        float s0 = low ? p[1] : p[0];
        float s1 = low ? q[1] : q[0];
        float v0 = __shfl_xor_sync(0xffffffffu, s0, 2);
        float v1 = __shfl_xor_sync(0xffffffffu, s1, 2);
        p[0] = (low ? p[0] : p[1]) + v0;
        q[0] = (low ? q[0] : q[1]) + v1;
    }
    r0 = p[0] + __shfl_xor_sync(0xffffffffu, p[0], 1);
    r1 = q[0] + __shfl_xor_sync(0xffffffffu, q[0], 1);
}

__device__ __forceinline__ void squash2(float s0, float s1, float& v0, float& v1) {
    float n0 = s0 * s0, n1 = s1 * s1;
#pragma unroll
    for (int o = 16; o; o >>= 1) {
        n0 += __shfl_xor_sync(0xffffffffu, n0, o);
        n1 += __shfl_xor_sync(0xffffffffu, n1, o);
    }
    v0 = (n0 / (1.f + n0)) / (sqrtf(n0) + 1e-8f) * s0;
    v1 = (n1 / (1.f + n1)) / (sqrtf(n1) + 1e-8f) * s1;
}

__global__ void __launch_bounds__(512)
capsule_routing_kernel(float* __restrict__ out, int batch) {
    const int gw = (int)((blockIdx.x * blockDim.x + threadIdx.x) >> 5);
    const int lane = threadIdx.x & 31;
    const int row0 = gw * 2;
    if (row0 >= batch) return;

    const float* ur0 = g_u + (size_t)row0 * N_DIM;
    const float* ur1 = ur0 + N_DIM;
    float u0[NUM_CAPS], u1[NUM_CAPS];
#pragma unroll
    for (int c = 0; c < NUM_CAPS; c++) {
        u0[c] = ur0[c * OUT_DIM + lane];
        u1[c] = ur1[c * OUT_DIM + lane];
    }

    float b0 = 0.f, b1 = 0.f;
    float v0, v1;

    {
        float s0 = u0[0], s1 = u1[0];
#pragma unroll
        for (int c = 1; c < NUM_CAPS; c++) { s0 += u0[c]; s1 += u1[c]; }
        s0 *= (1.f / 16.f); s1 *= (1.f / 16.f);
        squash2(s0, s1, v0, v1);
        float p[NUM_CAPS], q[NUM_CAPS];
#pragma unroll
        for (int c = 0; c < NUM_CAPS; c++) { p[c] = u0[c] * v0; q[c] = u1[c] * v1; }
        float d0, d1;
        rs16_dual(p, q, lane, d0, d1);
        b0 += d0; b1 += d1;
    }

#pragma unroll
    for (int it = 1; it < 3; it++) {
        float m0 = b0, m1 = b1;
#pragma unroll
        for (int o = 2; o <= 16; o <<= 1) {
            m0 = fmaxf(m0, __shfl_xor_sync(0xffffffffu, m0, o));
            m1 = fmaxf(m1, __shfl_xor_sync(0xffffffffu, m1, o));
        }
        float e0 = __expf(b0 - m0), e1 = __expf(b1 - m1);
        float t0 = e0, t1 = e1;
#pragma unroll
        for (int o = 2; o <= 16; o <<= 1) {
            t0 += __shfl_xor_sync(0xffffffffu, t0, o);
            t1 += __shfl_xor_sync(0xffffffffu, t1, o);
        }
        const float cw0 = e0 / t0, cw1 = e1 / t1;

        float s0 = 0.f, s1 = 0.f;
#pragma unroll
        for (int c = 0; c < NUM_CAPS; c++) {
            s0 = fmaf(__shfl_sync(0xffffffffu, cw0, 2 * c), u0[c], s0);
            s1 = fmaf(__shfl_sync(0xffffffffu, cw1, 2 * c), u1[c], s1);
        }
        squash2(s0, s1, v0, v1);

        if (it < 2) {
            float p[NUM_CAPS], q[NUM_CAPS];
#pragma unroll
            for (int c = 0; c < NUM_CAPS; c++) { p[c] = u0[c] * v0; q[c] = u1[c] * v1; }
            float d0, d1;
            rs16_dual(p, q, lane, d0, d1);
            b0 += d0; b1 += d1;
        }
    }

    out[(size_t)row0 * OUT_DIM + lane] = v0;
    out[(size_t)(row0 + 1) * OUT_DIM + lane] = v1;
}

// ---------------------------------------------------------------------------
extern "C" void kernel_launch(void* const* d_in, const int* in_sizes, int n_in,
                              void* d_out, int out_size) {
    const float* X = (const float*)d_in[0];   // [batch, 512]
    const float* W = (const float*)d_in[1];   // [512, 512]
    float* out = (float*)d_out;               // [batch, 32]

    const int batch = in_sizes[0] / K_DIM;    // 32768

    split_w_kernel<<<128, 256>>>(W);

    cudaFuncSetAttribute(capsule_gemm_kernel,
                         cudaFuncAttributeMaxDynamicSharedMemorySize, SMEM_POOL);
    dim3 ggrid(N_DIM / BN, batch / BM);       // (4, 256)
    capsule_gemm_kernel<<<ggrid, 256, SMEM_POOL>>>(X);

    const int rwarps = batch / 2;             // 2 rows per warp
    capsule_routing_kernel<<<(rwarps * 32) / 512, 512>>>(out, batch);
}

// round 17
// speedup vs baseline: 1.1437x; 1.0097x over previous
#include <cuda_runtime.h>
#include <cuda_fp16.h>
#include <cstdint>

// CapsuleLayer: v = routing(reshape(x @ W, [B,16,32]))
//   x: [32768, 512] f32, W: [512, 512] f32, out v: [32768, 32] f32
//
// R8 champion + L2 residency hints (createpolicy/cache_hint form — the only
// width-flexible encoding this toolchain accepts):
// K1: split_W -> g_Wp (hi/lo fp16 pairs, k-major), 4-wide vectorized
// K2: GEMM u = hh + hl + lh (fp32-accurate FP16 split, m16n8k16),
//     128x128 tile, 3-stage cp.async pipeline for B, LDG+pack+STS for A.
//     X loads evict_first (stream-once), u stores evict_last.
// K3: routing, 2 rows per warp (dual interleaved shuffle chains) -> out

#define K_DIM 512
#define N_DIM 512
#define NUM_CAPS 16
#define OUT_DIM 32
#define MAX_BATCH 32768
#define NKPALL (K_DIM / 2)

#define BM 128
#define BN 128
#define BK 16
#define NKP (BK / 2)            // 8 k-pairs per stage
#define NKT (K_DIM / BK)        // 32 stages
#define NSTG 3                  // smem ring depth
#define TS 132                  // tile row stride (uint2 units)

#define TILE_BYTES (NSTG * NKP * TS * 8)
#define SMEM_POOL (2 * TILE_BYTES)    // 50688 -> 2 CTAs/SM

__device__ float g_u[(size_t)MAX_BATCH * N_DIM];      // 64 MB
__device__ uint2 g_Wp[(size_t)NKPALL * N_DIM];        // 2 MB

__device__ __forceinline__ void split16(float x, __half& h, __half& l) {
    h = __float2half_rn(x);
    l = __float2half_rn(x - __half2float(h));
}
__device__ __forceinline__ uint2 pack_pair(float v0, float v1) {
    __half h0, l0, h1, l1;
    split16(v0, h0, l0);
    split16(v1, h1, l1);
    uint2 r;
    __half2 hh = __halves2half2(h0, h1);
    __half2 ll = __halves2half2(l0, l1);
    r.x = *reinterpret_cast<uint32_t*>(&hh);
    r.y = *reinterpret_cast<uint32_t*>(&ll);
    return r;
}
__device__ __forceinline__ void mma_m16n8k16_f16(float d[4], const uint32_t a[4],
                                                 const uint32_t b[2]) {
    asm volatile(
        "mma.sync.aligned.m16n8k16.row.col.f32.f16.f16.f32 "
        "{%0,%1,%2,%3}, {%4,%5,%6,%7}, {%8,%9}, {%0,%1,%2,%3};\n"
        : "+f"(d[0]), "+f"(d[1]), "+f"(d[2]), "+f"(d[3])
        : "r"(a[0]), "r"(a[1]), "r"(a[2]), "r"(a[3]), "r"(b[0]), "r"(b[1]));
}
__device__ __forceinline__ uint32_t smem_u32(const void* p) {
    return (uint32_t)__cvta_generic_to_shared(p);
}
__device__ __forceinline__ void cp_async16(uint32_t dst, const void* src) {
    asm volatile("cp.async.cg.shared.global [%0], [%1], 16;\n"
                 :: "r"(dst), "l"(src) : "memory");
}
// stream-once load: read-only, evict-first policy via cache_hint
__device__ __forceinline__ float4 ldg_ef4(const float* p) {
    float4 v;
    asm volatile(
        "{\n\t.reg .b64 pol;\n\t"
        "createpolicy.fractional.L2::evict_first.b64 pol, 1.0;\n\t"
        "ld.global.nc.L2::cache_hint.v4.f32 {%0,%1,%2,%3}, [%4], pol;\n\t}"
        : "=f"(v.x), "=f"(v.y), "=f"(v.z), "=f"(v.w) : "l"(p));
    return v;
}
// producer store: keep in L2 for the consumer kernel
__device__ __forceinline__ void stg_el2(float* p, float a, float b) {
    asm volatile(
        "{\n\t.reg .b64 pol;\n\t"
        "createpolicy.fractional.L2::evict_last.b64 pol, 1.0;\n\t"
        "st.global.L2::cache_hint.v2.f32 [%0], {%1,%2}, pol;\n\t}"
        :: "l"(p), "f"(a), "f"(b) : "memory");
}

// ---------------------------------------------------------------------------
// K1: W [512 k][512 n] f32 -> g_Wp [256 kp][512 n] uint2, 4 n per thread
// ---------------------------------------------------------------------------
__global__ void split_w_kernel(const float* __restrict__ W) {
    const int idx = blockIdx.x * blockDim.x + threadIdx.x;   // 32768 threads
    const int kp = idx >> 7;
    const int n4 = (idx & 127) << 2;
    float4 r0 = *reinterpret_cast<const float4*>(W + (size_t)(2 * kp) * N_DIM + n4);
    float4 r1 = *reinterpret_cast<const float4*>(W + (size_t)(2 * kp + 1) * N_DIM + n4);
    uint2* dst = &g_Wp[(size_t)kp * N_DIM + n4];
    uint2 p0 = pack_pair(r0.x, r1.x);
    uint2 p1 = pack_pair(r0.y, r1.y);
    uint2 p2 = pack_pair(r0.z, r1.z);
    uint2 p3 = pack_pair(r0.w, r1.w);
    *reinterpret_cast<uint4*>(dst)     = make_uint4(p0.x, p0.y, p1.x, p1.y);
    *reinterpret_cast<uint4*>(dst + 2) = make_uint4(p2.x, p2.y, p3.x, p3.y);
}

// ---------------------------------------------------------------------------
// K2: GEMM C[M,512] = X @ W, 128x128 tile, 256 thr (8 warps, 4m x 2n),
// warp tile 32x64 = 2 x 8 m16n8k16 frags, 3-stage cp.async pipeline.
// ---------------------------------------------------------------------------
__global__ void __launch_bounds__(256, 2)
capsule_gemm_kernel(const float* __restrict__ X) {
    extern __shared__ __align__(16) char smem[];
    typedef uint2 Tile[NKP][TS];
    Tile* Xs = reinterpret_cast<Tile*>(smem);                 // [NSTG]
    Tile* Ws = reinterpret_cast<Tile*>(smem + TILE_BYTES);    // [NSTG]

    const int tid = threadIdx.x;
    const int n0 = blockIdx.x * BN;
    const int m0 = blockIdx.y * BM;

    const int warp = tid >> 5;
    const int lane = tid & 31;
    const int wm = warp >> 1;
    const int wn = warp & 1;
    const int g = lane >> 2;
    const int t = lane & 3;

    // A staging: row xr, 8 k at xk8 -> 4 kp
    const int xr  = tid >> 1;
    const int xk8 = (tid & 1) << 3;
    const int p0  = (tid & 1) << 2;
    // B staging (cp.async): kp row wkp, 4 uint2 at wn4 (2 x 16B)
    const int wkp = tid >> 5;
    const int wn4 = (tid & 31) << 2;

    float acc[2][8][4];
#pragma unroll
    for (int i = 0; i < 2; i++)
#pragma unroll
        for (int j = 0; j < 8; j++)
#pragma unroll
            for (int q = 0; q < 4; q++) acc[i][j][q] = 0.f;

    const float* Asrc = X + (size_t)(m0 + xr) * K_DIM + xk8;
    const uint2* Bsrc = g_Wp + (size_t)wkp * N_DIM + n0 + wn4;

    float4 xa0, xa1;

    auto ldgA = [&](int kt) {
        xa0 = ldg_ef4(Asrc + kt * BK);
        xa1 = ldg_ef4(Asrc + kt * BK + 4);
    };
    auto stsA = [&](int s) {
        Xs[s][p0 + 0][xr] = pack_pair(xa0.x, xa0.y);
        Xs[s][p0 + 1][xr] = pack_pair(xa0.z, xa0.w);
        Xs[s][p0 + 2][xr] = pack_pair(xa1.x, xa1.y);
        Xs[s][p0 + 3][xr] = pack_pair(xa1.z, xa1.w);
    };
    auto asyncB = [&](int kt, int s) {
        const uint2* src = Bsrc + (size_t)kt * NKP * N_DIM;
        const uint32_t dst = smem_u32(&Ws[s][wkp][wn4]);
        cp_async16(dst, src);
        cp_async16(dst + 16, src + 2);
        asm volatile("cp.async.commit_group;\n" ::: "memory");
    };

    // term-inner compute (champion order, bit-identical accumulation)
    auto compute = [&](int s) {
        uint32_t aH[2][4], aL[2][4];
#pragma unroll
        for (int i = 0; i < 2; i++) {
            const int mr = wm * 32 + i * 16 + g;
            uint2 A0 = Xs[s][t][mr];
            uint2 A1 = Xs[s][t][mr + 8];
            uint2 A2 = Xs[s][t + 4][mr];
            uint2 A3 = Xs[s][t + 4][mr + 8];
            aH[i][0] = A0.x; aL[i][0] = A0.y;
            aH[i][1] = A1.x; aL[i][1] = A1.y;
            aH[i][2] = A2.x; aL[i][2] = A2.y;
            aH[i][3] = A3.x; aL[i][3] = A3.y;
        }
#pragma unroll
        for (int j = 0; j < 8; j++) {
            const int nc = wn * 64 + j * 8 + g;
            uint2 B0 = Ws[s][t][nc];
            uint2 B1 = Ws[s][t + 4][nc];
            uint32_t bH[2] = {B0.x, B1.x};
            uint32_t bL[2] = {B0.y, B1.y};
#pragma unroll
            for (int i = 0; i < 2; i++) {
                mma_m16n8k16_f16(acc[i][j], aH[i], bH);
                mma_m16n8k16_f16(acc[i][j], aH[i], bL);
                mma_m16n8k16_f16(acc[i][j], aL[i], bH);
            }
        }
    };

    // prologue: fill stages 0, 1
    ldgA(0); asyncB(0, 0); stsA(0);
    ldgA(1); asyncB(1, 1); stsA(1);
    asm volatile("cp.async.wait_group 1;\n" ::: "memory");   // B0 done
    __syncthreads();

    int s = 0;
    for (int kt = 0; kt < NKT; kt++) {
        if (kt + 2 < NKT) {
            ldgA(kt + 2);
            asyncB(kt + 2, (s + 2 >= NSTG) ? s + 2 - NSTG : s + 2);
        }
        compute(s);
        if (kt + 2 < NKT) stsA((s + 2 >= NSTG) ? s + 2 - NSTG : s + 2);
        if (kt + 1 < NKT) {
            if (kt + 2 < NKT)
                asm volatile("cp.async.wait_group 1;\n" ::: "memory");
            else
                asm volatile("cp.async.wait_group 0;\n" ::: "memory");
            __syncthreads();
        }
        s = (s + 1 >= NSTG) ? 0 : s + 1;
    }

    // epilogue -> g_u (evict_last policy: stay L2-resident for routing)
#pragma unroll
    for (int i = 0; i < 2; i++) {
#pragma unroll
        for (int j = 0; j < 8; j++) {
            const int row = m0 + wm * 32 + i * 16 + g;
            const int col = n0 + wn * 64 + j * 8 + t * 2;
            stg_el2(&g_u[(size_t)row * N_DIM + col], acc[i][j][0], acc[i][j][1]);
            stg_el2(&g_u[(size_t)(row + 8) * N_DIM + col], acc[i][j][2], acc[i][j][3]);
        }
    }
}

// ---------------------------------------------------------------------------
// K3: routing, one warp per TWO rows (dual interleaved chains), lane = dim.
// ---------------------------------------------------------------------------
__device__ __forceinline__ void rs16_dual(float p[NUM_CAPS], float q[NUM_CAPS],
                                          int lane, float& r0, float& r1) {
    {
        const bool low = (lane & 16) == 0;
#pragma unroll
        for (int i = 0; i < 8; i++) {
            float s0 = low ? p[i + 8] : p[i];
            float s1 = low ? q[i + 8] : q[i];
            float v0 = __shfl_xor_sync(0xffffffffu, s0, 16);
            float v1 = __shfl_xor_sync(0xffffffffu, s1, 16);
            p[i] = (low ? p[i] : p[i + 8]) + v0;
            q[i] = (low ? q[i] : q[i + 8]) + v1;
        }
    }
    {
        const bool low = (lane & 8) == 0;
#pragma unroll
        for (int i = 0; i < 4; i++) {
            float s0 = low ? p[i + 4] : p[i];
            float s1 = low ? q[i + 4] : q[i];
            float v0 = __shfl_xor_sync(0xffffffffu, s0, 8);
            float v1 = __shfl_xor_sync(0xffffffffu, s1, 8);
            p[i] = (low ? p[i] : p[i + 4]) + v0;
            q[i] = (low ? q[i] : q[i + 4]) + v1;
        }
    }
    {
        const bool low = (lane & 4) == 0;
#pragma unroll
        for (int i = 0; i < 2; i++) {
            float s0 = low ? p[i + 2] : p[i];
            float s1 = low ? q[i + 2] : q[i];
            float v0 = __shfl_xor_sync(0xffffffffu, s0, 4);
            float v1 = __shfl_xor_sync(0xffffffffu, s1, 4);
            p[i] = (low ? p[i] : p[i + 2]) + v0;
            q[i] = (low ? q[i] : q[i + 2]) + v1;
        }
    }
    {
        const bool low = (lane & 2) == 0;
        float s0 = low ? p[1] : p[0];
        float s1 = low ? q[1] : q[0];
        float v0 = __shfl_xor_sync(0xffffffffu, s0, 2);
        float v1 = __shfl_xor_sync(0xffffffffu, s1, 2);
        p[0] = (low ? p[0] : p[1]) + v0;
        q[0] = (low ? q[0] : q[1]) + v1;
    }
    r0 = p[0] + __shfl_xor_sync(0xffffffffu, p[0], 1);
    r1 = q[0] + __shfl_xor_sync(0xffffffffu, q[0], 1);
}

__device__ __forceinline__ void squash2(float s0, float s1, float& v0, float& v1) {
    float n0 = s0 * s0, n1 = s1 * s1;
#pragma unroll
    for (int o = 16; o; o >>= 1) {
        n0 += __shfl_xor_sync(0xffffffffu, n0, o);
        n1 += __shfl_xor_sync(0xffffffffu, n1, o);
    }
    v0 = (n0 / (1.f + n0)) / (sqrtf(n0) + 1e-8f) * s0;
    v1 = (n1 / (1.f + n1)) / (sqrtf(n1) + 1e-8f) * s1;
}

__global__ void __launch_bounds__(256)
capsule_routing_kernel(float* __restrict__ out, int batch) {
    const int gw = (int)((blockIdx.x * blockDim.x + threadIdx.x) >> 5);
    const int lane = threadIdx.x & 31;
    const int row0 = gw * 2;
    if (row0 >= batch) return;

    const float* ur0 = g_u + (size_t)row0 * N_DIM;
    const float* ur1 = ur0 + N_DIM;
    float u0[NUM_CAPS], u1[NUM_CAPS];
#pragma unroll
    for (int c = 0; c < NUM_CAPS; c++) {
        u0[c] = __ldg(ur0 + c * OUT_DIM + lane);
        u1[c] = __ldg(ur1 + c * OUT_DIM + lane);
    }

    float b0 = 0.f, b1 = 0.f;
    float v0, v1;

    {
        float s0 = u0[0], s1 = u1[0];
#pragma unroll
        for (int c = 1; c < NUM_CAPS; c++) { s0 += u0[c]; s1 += u1[c]; }
        s0 *= (1.f / 16.f); s1 *= (1.f / 16.f);
        squash2(s0, s1, v0, v1);
        float p[NUM_CAPS], q[NUM_CAPS];
#pragma unroll
        for (int c = 0; c < NUM_CAPS; c++) { p[c] = u0[c] * v0; q[c] = u1[c] * v1; }
        float d0, d1;
        rs16_dual(p, q, lane, d0, d1);
        b0 += d0; b1 += d1;
    }

#pragma unroll
    for (int it = 1; it < 3; it++) {
        float m0 = b0, m1 = b1;
#pragma unroll
        for (int o = 2; o <= 16; o <<= 1) {
            m0 = fmaxf(m0, __shfl_xor_sync(0xffffffffu, m0, o));
            m1 = fmaxf(m1, __shfl_xor_sync(0xffffffffu, m1, o));
        }
        float e0 = __expf(b0 - m0), e1 = __expf(b1 - m1);
        float t0 = e0, t1 = e1;
#pragma unroll
        for (int o = 2; o <= 16; o <<= 1) {
            t0 += __shfl_xor_sync(0xffffffffu, t0, o);
            t1 += __shfl_xor_sync(0xffffffffu, t1, o);
        }
        const float cw0 = e0 / t0, cw1 = e1 / t1;

        float s0 = 0.f, s1 = 0.f;
#pragma unroll
        for (int c = 0; c < NUM_CAPS; c++) {
            s0 = fmaf(__shfl_sync(0xffffffffu, cw0, 2 * c), u0[c], s0);
            s1 = fmaf(__shfl_sync(0xffffffffu, cw1, 2 * c), u1[c], s1);
        }
        squash2(s0, s1, v0, v1);

        if (it < 2) {
            float p[NUM_CAPS], q[NUM_CAPS];
#pragma unroll
            for (int c = 0; c < NUM_CAPS; c++) { p[c] = u0[c] * v0; q[c] = u1[c] * v1; }
            float d0, d1;
            rs16_dual(p, q, lane, d0, d1);
            b0 += d0; b1 += d1;
        }
    }

    out[(size_t)row0 * OUT_DIM + lane] = v0;
    out[(size_t)(row0 + 1) * OUT_DIM + lane] = v1;
}

// ---------------------------------------------------------------------------
extern "C" void kernel_launch(void* const* d_in, const int* in_sizes, int n_in,
                              void* d_out, int out_size) {
    const float* X = (const float*)d_in[0];   // [batch, 512]
    const float* W = (const float*)d_in[1];   // [512, 512]
    float* out = (float*)d_out;               // [batch, 32]

    const int batch = in_sizes[0] / K_DIM;    // 32768

    split_w_kernel<<<128, 256>>>(W);

    cudaFuncSetAttribute(capsule_gemm_kernel,
                         cudaFuncAttributeMaxDynamicSharedMemorySize, SMEM_POOL);
    dim3 ggrid(N_DIM / BN, batch / BM);       // (4, 256)
    capsule_gemm_kernel<<<ggrid, 256, SMEM_POOL>>>(X);

    const int rwarps = batch / 2;             // 2 rows per warp
    capsule_routing_kernel<<<(rwarps * 32) / 256, 256>>>(out, batch);
}